// round 6
// baseline (speedup 1.0000x reference)
#include <cuda_runtime.h>
#include <cuda_fp16.h>
#include <cuda_bf16.h>

#define BB 8
#define TT 12
#define NN 1500
#define HH 64
#define BNS 12000
#define OUTD 3

typedef unsigned long long ull;

// ---- scratch (device globals, no runtime alloc) ----
static __device__ float g_hs0[TT * HH * BNS + 64];  // layer0 hidden [t][c][s]
static __device__ float g_h  [BNS * HH];            // lstm final hidden [s][c]
static __device__ __half g_hph[BNS * HH];           // gat projected feats (fp16)
static __device__ float g_es [BNS * 4];
static __device__ float g_ed [BNS * 4];
static __device__ float g_gmax[BB * 4];             // per (b,h) max of ed
static __device__ float g_ho [BNS * HH];            // gat0 out
static __device__ float g_h2 [BNS * HH];            // gat1 out

__device__ __forceinline__ float sigf(float x)   { return 1.0f / (1.0f + __expf(-x)); }
__device__ __forceinline__ float tanh_f(float x) { return 1.0f - 2.0f / (1.0f + __expf(2.0f * x)); }
__device__ __forceinline__ float lrelu(float x)  { return fmaxf(x, 0.2f * x); }

__device__ __forceinline__ ull pack2(float a, float b) {
    ull r; asm("mov.b64 %0, {%1,%2};" : "=l"(r) : "f"(a), "f"(b)); return r;
}
__device__ __forceinline__ ull pack1(float a) {
    ull r; asm("mov.b64 %0, {%1,%1};" : "=l"(r) : "f"(a)); return r;
}
__device__ __forceinline__ ull ffma2(ull a, ull b, ull c) {
    ull d; asm("fma.rn.f32x2 %0, %1, %2, %3;" : "=l"(d) : "l"(a), "l"(b), "l"(c)); return d;
}
__device__ __forceinline__ float2 unpack2(ull v) {
    float lo, hi; asm("mov.b64 {%0,%1}, %2;" : "=f"(lo), "=f"(hi) : "l"(v));
    return make_float2(lo, hi);
}

__device__ __forceinline__ unsigned smem_u32(const void* p) {
    return (unsigned)__cvta_generic_to_shared(p);
}
__device__ __forceinline__ void ldsm_x4(unsigned& r0, unsigned& r1, unsigned& r2, unsigned& r3, unsigned a) {
    asm volatile("ldmatrix.sync.aligned.m8n8.x4.shared.b16 {%0,%1,%2,%3}, [%4];"
                 : "=r"(r0), "=r"(r1), "=r"(r2), "=r"(r3) : "r"(a));
}
__device__ __forceinline__ void ldsm_x4t(unsigned& r0, unsigned& r1, unsigned& r2, unsigned& r3, unsigned a) {
    asm volatile("ldmatrix.sync.aligned.m8n8.x4.trans.shared.b16 {%0,%1,%2,%3}, [%4];"
                 : "=r"(r0), "=r"(r1), "=r"(r2), "=r"(r3) : "r"(a));
}
__device__ __forceinline__ void mma16816(float& c0, float& c1, float& c2, float& c3,
                                         unsigned a0, unsigned a1, unsigned a2, unsigned a3,
                                         unsigned b0, unsigned b1) {
    asm volatile("mma.sync.aligned.m16n8k16.row.col.f32.f16.f16.f32 "
                 "{%0,%1,%2,%3}, {%4,%5,%6,%7}, {%8,%9}, {%0,%1,%2,%3};"
                 : "+f"(c0), "+f"(c1), "+f"(c2), "+f"(c3)
                 : "r"(a0), "r"(a1), "r"(a2), "r"(a3), "r"(b0), "r"(b1));
}

// ================= LSTM layer 0 =================
__global__ void __launch_bounds__(256, 2) lstm0_kernel(
    const float* __restrict__ x, const float* __restrict__ Wih,
    const float* __restrict__ Whh, const float* __restrict__ bih,
    const float* __restrict__ bhh)
{
    extern __shared__ float sm[];
    float* Whh_s = sm;            // 256*68
    float* h_s   = sm + 17408;    // [c][s]
    const int tid = threadIdx.x;
    for (int i = tid; i < 16384; i += 256) Whh_s[(i >> 6) * 68 + (i & 63)] = Whh[i];
    for (int i = tid; i < 2048; i += 256) h_s[i] = 0.0f;

    const int gid = tid >> 2, slot = tid & 3;
    const int sb = blockIdx.x * 32;

    float wih[4], bs[4];
#pragma unroll
    for (int g = 0; g < 4; g++) {
        int k = g * 64 + gid;
        wih[g] = Wih[k];
        bs[g]  = bih[k] + bhh[k];
    }
    int xoff[8];
#pragma unroll
    for (int p = 0; p < 4; p++) {
        int s0 = 2 * slot + 8 * p;
#pragma unroll
        for (int q = 0; q < 2; q++) {
            int seq = sb + s0 + q;
            int b = seq / NN, n = seq % NN;
            xoff[2 * p + q] = b * (TT * NN) + n;
        }
    }
    float cs[8];
#pragma unroll
    for (int i = 0; i < 8; i++) cs[i] = 0.0f;
    __syncthreads();

    for (int t = 0; t < TT; t++) {
        float xv[8];
#pragma unroll
        for (int i = 0; i < 8; i++) xv[i] = x[xoff[i] + t * NN];
        ull acc[4][4];
#pragma unroll
        for (int g = 0; g < 4; g++)
#pragma unroll
            for (int p = 0; p < 4; p++)
                acc[g][p] = pack2(bs[g] + wih[g] * xv[2 * p],
                                  bs[g] + wih[g] * xv[2 * p + 1]);
#pragma unroll 1
        for (int c = 0; c < 64; c += 2) {
            ull wp[4][2];
#pragma unroll
            for (int g = 0; g < 4; g++) {
                float2 w = *reinterpret_cast<const float2*>(&Whh_s[(g * 64 + gid) * 68 + c]);
                wp[g][0] = pack1(w.x); wp[g][1] = pack1(w.y);
            }
#pragma unroll
            for (int p = 0; p < 4; p++) {
                int s0 = 2 * slot + 8 * p;
                ull h0 = *reinterpret_cast<const ull*>(&h_s[(c + 0) * 32 + s0]);
                ull h1 = *reinterpret_cast<const ull*>(&h_s[(c + 1) * 32 + s0]);
#pragma unroll
                for (int g = 0; g < 4; g++) {
                    acc[g][p] = ffma2(wp[g][0], h0, acc[g][p]);
                    acc[g][p] = ffma2(wp[g][1], h1, acc[g][p]);
                }
            }
        }
        __syncthreads();
#pragma unroll
        for (int p = 0; p < 4; p++) {
            float2 iv = unpack2(acc[0][p]), fv = unpack2(acc[1][p]);
            float2 gv = unpack2(acc[2][p]), ov = unpack2(acc[3][p]);
            float c0 = sigf(fv.x) * cs[2 * p]     + sigf(iv.x) * tanh_f(gv.x);
            float c1 = sigf(fv.y) * cs[2 * p + 1] + sigf(iv.y) * tanh_f(gv.y);
            cs[2 * p] = c0; cs[2 * p + 1] = c1;
            float ha = sigf(ov.x) * tanh_f(c0), hb = sigf(ov.y) * tanh_f(c1);
            int s0 = 2 * slot + 8 * p;
            *reinterpret_cast<float2*>(&h_s[gid * 32 + s0]) = make_float2(ha, hb);
            *reinterpret_cast<float2*>(&g_hs0[(t * 64 + gid) * BNS + sb + s0]) = make_float2(ha, hb);
        }
        __syncthreads();
    }
}

// ================= LSTM layer 1 (fused input-proj + recurrence) =================
__global__ void __launch_bounds__(512, 1) lstm1f_kernel(
    const float* __restrict__ Wih, const float* __restrict__ Whh,
    const float* __restrict__ bih, const float* __restrict__ bhh)
{
    extern __shared__ float sm[];
    float* Whh_s = sm;             // 17408
    float* Wih_s = sm + 17408;     // 17408
    float* h_s   = sm + 34816;     // 4096 [c][s]
    float* x_s   = sm + 38912;     // 2*4096 double buffer
    const int tid = threadIdx.x;
    for (int i = tid; i < 16384; i += 512) {
        int o = (i >> 6) * 68 + (i & 63);
        Whh_s[o] = Whh[i];
        Wih_s[o] = Wih[i];
    }
    for (int i = tid; i < 4096; i += 512) h_s[i] = 0.0f;

    const int gid = tid >> 3, slot = tid & 7;
    const int sb = blockIdx.x * 64;

    ull bsp[4];
#pragma unroll
    for (int g = 0; g < 4; g++) {
        int k = g * 64 + gid;
        bsp[g] = pack1(bih[k] + bhh[k]);
    }
    float cs[8];
#pragma unroll
    for (int i = 0; i < 8; i++) cs[i] = 0.0f;

    for (int i = tid; i < 2048; i += 512) {
        int c = i >> 5, sl = (i & 31) * 2;
        *reinterpret_cast<float2*>(&x_s[c * 64 + sl]) =
            *reinterpret_cast<const float2*>(&g_hs0[(0 * 64 + c) * BNS + sb + sl]);
    }
    __syncthreads();

    for (int t = 0; t < TT; t++) {
        const float* xcur = x_s + (t & 1) * 4096;
        ull acc[4][4];
#pragma unroll
        for (int g = 0; g < 4; g++)
#pragma unroll
            for (int p = 0; p < 4; p++) acc[g][p] = bsp[g];
#pragma unroll 1
        for (int c = 0; c < 64; c += 2) {
            ull wh[4][2], wi[4][2];
#pragma unroll
            for (int g = 0; g < 4; g++) {
                int o = (g * 64 + gid) * 68 + c;
                float2 a = *reinterpret_cast<const float2*>(&Whh_s[o]);
                float2 b = *reinterpret_cast<const float2*>(&Wih_s[o]);
                wh[g][0] = pack1(a.x); wh[g][1] = pack1(a.y);
                wi[g][0] = pack1(b.x); wi[g][1] = pack1(b.y);
            }
#pragma unroll
            for (int p = 0; p < 4; p++) {
                int s0 = 2 * slot + 16 * p;
                ull h0 = *reinterpret_cast<const ull*>(&h_s[(c + 0) * 64 + s0]);
                ull h1 = *reinterpret_cast<const ull*>(&h_s[(c + 1) * 64 + s0]);
                ull x0 = *reinterpret_cast<const ull*>(&xcur[(c + 0) * 64 + s0]);
                ull x1 = *reinterpret_cast<const ull*>(&xcur[(c + 1) * 64 + s0]);
#pragma unroll
                for (int g = 0; g < 4; g++) {
                    acc[g][p] = ffma2(wh[g][0], h0, acc[g][p]);
                    acc[g][p] = ffma2(wh[g][1], h1, acc[g][p]);
                    acc[g][p] = ffma2(wi[g][0], x0, acc[g][p]);
                    acc[g][p] = ffma2(wi[g][1], x1, acc[g][p]);
                }
            }
        }
        __syncthreads();
#pragma unroll
        for (int p = 0; p < 4; p++) {
            float2 iv = unpack2(acc[0][p]), fv = unpack2(acc[1][p]);
            float2 gv = unpack2(acc[2][p]), ov = unpack2(acc[3][p]);
            float c0 = sigf(fv.x) * cs[2 * p]     + sigf(iv.x) * tanh_f(gv.x);
            float c1 = sigf(fv.y) * cs[2 * p + 1] + sigf(iv.y) * tanh_f(gv.y);
            cs[2 * p] = c0; cs[2 * p + 1] = c1;
            float ha = sigf(ov.x) * tanh_f(c0), hb = sigf(ov.y) * tanh_f(c1);
            int s0 = 2 * slot + 16 * p;
            *reinterpret_cast<float2*>(&h_s[gid * 64 + s0]) = make_float2(ha, hb);
            if (t == TT - 1) {
                int seq = sb + s0;
                g_h[seq * HH + gid] = ha;
                g_h[(seq + 1) * HH + gid] = hb;
            }
        }
        if (t + 1 < TT) {
            for (int i = tid; i < 2048; i += 512) {
                int c = i >> 5, sl = (i & 31) * 2;
                *reinterpret_cast<float2*>(&x_s[((t + 1) & 1) * 4096 + c * 64 + sl]) =
                    *reinterpret_cast<const float2*>(&g_hs0[((t + 1) * 64 + c) * BNS + sb + sl]);
            }
        }
        __syncthreads();
    }
}

// ================= GAT prep: hp(fp16) = h @ W^T, e_src, e_dst =================
__global__ void __launch_bounds__(256) gat_prep_kernel(
    const float* __restrict__ hin, const float* __restrict__ W,
    const float* __restrict__ asrc, const float* __restrict__ adst)
{
    __shared__ float W_s[64 * 65];
    __shared__ float hin_s[4][64];
    __shared__ float hp_s[4][64];
    __shared__ float as_s[64], ad_s[64];
    const int tid = threadIdx.x;
    for (int i = tid; i < 4096; i += 256) W_s[(i >> 6) * 65 + (i & 63)] = W[i];
    const int ri = tid >> 6, k = tid & 63;
    const int r = blockIdx.x * 4 + ri;
    hin_s[ri][k] = hin[r * 64 + k];
    if (tid < 64) as_s[tid] = asrc[tid];
    else if (tid < 128) ad_s[tid - 64] = adst[tid - 64];
    __syncthreads();
    float acc = 0.0f;
#pragma unroll
    for (int c = 0; c < 64; c++) acc += W_s[k * 65 + c] * hin_s[ri][c];
    g_hph[r * 64 + k] = __float2half(acc);
    hp_s[ri][k] = acc;
    __syncthreads();
    if (tid < 32) {
        int rri = tid >> 3, h = (tid >> 1) & 3, w = tid & 1;
        const float* a = w ? ad_s : as_s;
        float d = 0.0f;
#pragma unroll
        for (int dd = 0; dd < 16; dd++) d += hp_s[rri][h * 16 + dd] * a[h * 16 + dd];
        int rr = blockIdx.x * 4 + rri;
        if (w) g_ed[rr * 4 + h] = d; else g_es[rr * 4 + h] = d;
    }
}

// ================= global per-(b,h) max of ed =================
__global__ void gmax_kernel() {
    const int w = blockIdx.x;          // 0..31
    const int b = w >> 2, h = w & 3;
    const int lane = threadIdx.x;
    float m = -1e30f;
    for (int j = lane; j < NN; j += 32)
        m = fmaxf(m, g_ed[(b * NN + j) * 4 + h]);
#pragma unroll
    for (int off = 16; off; off >>= 1)
        m = fmaxf(m, __shfl_xor_sync(0xffffffffu, m, off));
    if (lane == 0) g_gmax[w] = m;
}

// ================= GAT softmax + aggregate via mma.m16n8k16 =================
// block: 256 thr = 8 warps; 32 rows (2 segs x 16) x 4 heads; j-tiles of 64.
#define NTJ 24
__global__ void __launch_bounds__(256, 2) gat_agg2_kernel(
    const int* __restrict__ adj, float* __restrict__ out)
{
    extern __shared__ char smc[];
    __half* hp_s = (__half*)smc;                    // [64][72]      9216 B
    __half* p_s  = (__half*)(smc + 9216);           // [8][16][72]  18432 B
    float* ed_s  = (float*)(smc + 27648);           // [1536][4]    24576 B
    unsigned* adjm = (unsigned*)(smc + 52224);      // [64]           256 B
    float* psum_s  = (float*)(smc + 52480);         // [8][16]        512 B

    const int tid = threadIdx.x;
    const int b = blockIdx.y;
    const int i0 = blockIdx.x * 32;
    const int warp = tid >> 5, lane = tid & 31;
    const int h_w = warp & 3, seg = warp >> 2;
    const int iw0 = i0 + seg * 16;
    const int i_loc = lane >> 1, jhalf = lane & 1;
    const int i_row = iw0 + i_loc;
    const int irc = (i_row < NN) ? i_row : NN - 1;

    // stage ed for whole batch row
    for (int idx = tid; idx < 1536; idx += 256) {
        float4 v = make_float4(0.f, 0.f, 0.f, 0.f);
        if (idx < NN) v = reinterpret_cast<const float4*>(g_ed)[b * NN + idx];
        reinterpret_cast<float4*>(ed_s)[idx] = v;
    }

    const float es = g_es[(b * NN + irc) * 4 + h_w];
    const float M  = lrelu(es + g_gmax[b * 4 + h_w]);

    __half* pw = p_s + warp * (16 * 72);
    const unsigned pw_b  = smem_u32(pw);
    const unsigned hps_b = smem_u32(hp_s);

    float acc[8];
#pragma unroll
    for (int i = 0; i < 8; i++) acc[i] = 0.0f;
    float psl = 0.0f;

    for (int jt = 0; jt < NTJ; jt++) {
        const int jb = jt * 64;
        __syncthreads();
        // stage hp fp16 tile [64 j][64 ch] -> stride 72
        for (int k = tid; k < 512; k += 256) {
            int jl = k >> 3, co = (k & 7) * 8;
            int j = jb + jl;
            uint4 v = make_uint4(0u, 0u, 0u, 0u);
            if (j < NN) v = *reinterpret_cast<const uint4*>(&g_hph[(b * NN + j) * 64 + co]);
            *reinterpret_cast<uint4*>(&hp_s[jl * 72 + co]) = v;
        }
        // adjacency bitmask: 64 words (32 rows x 2 halves), ballot
#pragma unroll
        for (int p = 0; p < 8; p++) {
            int word = warp * 8 + p;
            int ii = i0 + (word >> 1);
            int jj = jb + (word & 1) * 32 + lane;
            int a = (ii < NN && jj < NN) ? adj[ii * NN + jj] : 0;
            unsigned m = __ballot_sync(0xffffffffu, a > 0);
            if (lane == 0) adjm[word] = m;
        }
        __syncthreads();

        // compute P (fp16) for this warp's 16 rows x 64 j (head h_w)
        {
            unsigned mword = adjm[(seg * 16 + i_loc) * 2 + jhalf];
            const float* edp = ed_s + (jb + jhalf * 32) * 4 + h_w;
            __half2* pst = reinterpret_cast<__half2*>(pw + i_loc * 72 + jhalf * 32);
#pragma unroll
            for (int q = 0; q < 32; q += 2) {
                float m0 = (float)((mword >> q) & 1u);
                float m1 = (float)((mword >> (q + 1)) & 1u);
                float p0 = m0 * __expf(lrelu(es + edp[q * 4]) - M);
                float p1 = m1 * __expf(lrelu(es + edp[(q + 1) * 4]) - M);
                psl += p0 + p1;
                pst[q >> 1] = __floats2half2_rn(p0, p1);
            }
        }
        __syncwarp();

        // MMA: 4 k-steps of 16
        const unsigned a_addr0 = pw_b + (lane & 15) * 144 + ((lane >> 4) * 8) * 2;
        const unsigned b_addr0 = hps_b + ((lane & 15) * 72 + h_w * 16 + (lane >> 4) * 8) * 2;
#pragma unroll
        for (int kt = 0; kt < 4; kt++) {
            unsigned a0, a1, a2, a3, b0, b1, b2, b3;
            ldsm_x4 (a0, a1, a2, a3, a_addr0 + kt * 32);
            ldsm_x4t(b0, b1, b2, b3, b_addr0 + kt * 16 * 144);
            mma16816(acc[0], acc[1], acc[2], acc[3], a0, a1, a2, a3, b0, b1);
            mma16816(acc[4], acc[5], acc[6], acc[7], a0, a1, a2, a3, b2, b3);
        }
    }

    // row sums
    psl += __shfl_xor_sync(0xffffffffu, psl, 1);
    if (jhalf == 0) psum_s[warp * 16 + i_loc] = psl;
    __syncwarp();

    const int r_lo = iw0 + (lane >> 2), r_hi = r_lo + 8;
    const float inv_lo = 1.0f / psum_s[warp * 16 + (lane >> 2)];
    const float inv_hi = 1.0f / psum_s[warp * 16 + (lane >> 2) + 8];
    const int cb = h_w * 16 + (lane & 3) * 2;
    if (r_lo < NN) {
        *reinterpret_cast<float2*>(&out[(b * NN + r_lo) * 64 + cb]) =
            make_float2(fmaxf(acc[0] * inv_lo, 0.f), fmaxf(acc[1] * inv_lo, 0.f));
        *reinterpret_cast<float2*>(&out[(b * NN + r_lo) * 64 + cb + 8]) =
            make_float2(fmaxf(acc[4] * inv_lo, 0.f), fmaxf(acc[5] * inv_lo, 0.f));
    }
    if (r_hi < NN) {
        *reinterpret_cast<float2*>(&out[(b * NN + r_hi) * 64 + cb]) =
            make_float2(fmaxf(acc[2] * inv_hi, 0.f), fmaxf(acc[3] * inv_hi, 0.f));
        *reinterpret_cast<float2*>(&out[(b * NN + r_hi) * 64 + cb + 8]) =
            make_float2(fmaxf(acc[6] * inv_hi, 0.f), fmaxf(acc[7] * inv_hi, 0.f));
    }
}

// ================= output head =================
__global__ void __launch_bounds__(256) head_kernel(
    const float* __restrict__ oW, const float* __restrict__ ob,
    float* __restrict__ out)
{
    int s = blockIdx.x * 256 + threadIdx.x;
    if (s >= BNS) return;
    int b = s / NN, n = s % NN;
    float a0 = ob[0], a1 = ob[1], a2 = ob[2];
#pragma unroll 8
    for (int c = 0; c < 64; c++) {
        float v = g_h2[s * 64 + c];
        a0 += oW[c] * v; a1 += oW[64 + c] * v; a2 += oW[128 + c] * v;
    }
    out[(b * OUTD + 0) * NN + n] = a0;
    out[(b * OUTD + 1) * NN + n] = a1;
    out[(b * OUTD + 2) * NN + n] = a2;
}

extern "C" void kernel_launch(void* const* d_in, const int* in_sizes, int n_in,
                              void* d_out, int out_size) {
    const float* x    = (const float*)d_in[0];
    const int*   adj  = (const int*)  d_in[1];
    const float* Wih0 = (const float*)d_in[2];
    const float* Whh0 = (const float*)d_in[3];
    const float* bih0 = (const float*)d_in[4];
    const float* bhh0 = (const float*)d_in[5];
    const float* Wih1 = (const float*)d_in[6];
    const float* Whh1 = (const float*)d_in[7];
    const float* bih1 = (const float*)d_in[8];
    const float* bhh1 = (const float*)d_in[9];
    const float* g0W  = (const float*)d_in[10];
    const float* g0as = (const float*)d_in[11];
    const float* g0ad = (const float*)d_in[12];
    const float* g1W  = (const float*)d_in[13];
    const float* g1as = (const float*)d_in[14];
    const float* g1ad = (const float*)d_in[15];
    const float* outW = (const float*)d_in[16];
    const float* outb = (const float*)d_in[17];
    float* out = (float*)d_out;

    cudaFuncSetAttribute(lstm0_kernel,     cudaFuncAttributeMaxDynamicSharedMemorySize, 77824);
    cudaFuncSetAttribute(lstm1f_kernel,    cudaFuncAttributeMaxDynamicSharedMemorySize, 188416);
    cudaFuncSetAttribute(gat_agg2_kernel,  cudaFuncAttributeMaxDynamicSharedMemorySize, 52992);

    float* g_h_p;  cudaGetSymbolAddress((void**)&g_h_p,  g_h);
    float* g_ho_p; cudaGetSymbolAddress((void**)&g_ho_p, g_ho);
    float* g_h2_p; cudaGetSymbolAddress((void**)&g_h2_p, g_h2);

    lstm0_kernel <<<375, 256, 77824>>>(x, Wih0, Whh0, bih0, bhh0);
    lstm1f_kernel<<<188, 512, 188416>>>(Wih1, Whh1, bih1, bhh1);

    gat_prep_kernel<<<3000, 256>>>(g_h_p, g0W, g0as, g0ad);
    gmax_kernel<<<32, 32>>>();
    gat_agg2_kernel<<<dim3(47, 8), 256, 52992>>>(adj, g_ho_p);

    gat_prep_kernel<<<3000, 256>>>(g_ho_p, g1W, g1as, g1ad);
    gmax_kernel<<<32, 32>>>();
    gat_agg2_kernel<<<dim3(47, 8), 256, 52992>>>(adj, g_h2_p);

    head_kernel<<<47, 256>>>(outW, outb, out);
}

// round 7
// speedup vs baseline: 1.1197x; 1.1197x over previous
#include <cuda_runtime.h>
#include <cuda_fp16.h>
#include <cuda_bf16.h>

#define BB 8
#define TT 12
#define NN 1500
#define HH 64
#define BNS 12000
#define OUTD 3

// ---- scratch (device globals, no runtime alloc) ----
static __device__ unsigned g_h0p[TT * BNS * HH];    // layer0 h packed (hi,lo) fp16
static __device__ float g_h  [BNS * HH];            // lstm final hidden [s][c]
static __device__ __half g_hph[BNS * HH];           // gat projected feats (fp16)
static __device__ float g_es [BNS * 4];
static __device__ float g_ed [BNS * 4];
static __device__ float g_gmax[BB * 4];
static __device__ float g_ho [BNS * HH];
static __device__ float g_h2 [BNS * HH];

__device__ __forceinline__ float sigf(float x)   { return 1.0f / (1.0f + __expf(-x)); }
__device__ __forceinline__ float tanh_f(float x) { return 1.0f - 2.0f / (1.0f + __expf(2.0f * x)); }
__device__ __forceinline__ float lrelu(float x)  { return fmaxf(x, 0.2f * x); }

__device__ __forceinline__ unsigned smem_u32(const void* p) {
    return (unsigned)__cvta_generic_to_shared(p);
}
__device__ __forceinline__ void ldsm_x4(unsigned& r0, unsigned& r1, unsigned& r2, unsigned& r3, unsigned a) {
    asm volatile("ldmatrix.sync.aligned.m8n8.x4.shared.b16 {%0,%1,%2,%3}, [%4];"
                 : "=r"(r0), "=r"(r1), "=r"(r2), "=r"(r3) : "r"(a));
}
__device__ __forceinline__ void ldsm_x4t(unsigned& r0, unsigned& r1, unsigned& r2, unsigned& r3, unsigned a) {
    asm volatile("ldmatrix.sync.aligned.m8n8.x4.trans.shared.b16 {%0,%1,%2,%3}, [%4];"
                 : "=r"(r0), "=r"(r1), "=r"(r2), "=r"(r3) : "r"(a));
}
__device__ __forceinline__ void mma16816(float& c0, float& c1, float& c2, float& c3,
                                         unsigned a0, unsigned a1, unsigned a2, unsigned a3,
                                         unsigned b0, unsigned b1) {
    asm volatile("mma.sync.aligned.m16n8k16.row.col.f32.f16.f16.f32 "
                 "{%0,%1,%2,%3}, {%4,%5,%6,%7}, {%8,%9}, {%0,%1,%2,%3};"
                 : "+f"(c0), "+f"(c1), "+f"(c2), "+f"(c3)
                 : "r"(a0), "r"(a1), "r"(a2), "r"(a3), "r"(b0), "r"(b1));
}

#define MMA2(NT, B0,B1,B2,B3, A0,A1,A2,A3) \
    mma16816(acc[2*(NT)][0],acc[2*(NT)][1],acc[2*(NT)][2],acc[2*(NT)][3],A0,A1,A2,A3,B0,B1); \
    mma16816(acc[2*(NT)+1][0],acc[2*(NT)+1][1],acc[2*(NT)+1][2],acc[2*(NT)+1][3],A0,A1,A2,A3,B2,B3)

// ================= unified tensor-core LSTM (LAYER 0 or 1) =================
// 192 thr = 6 warps, 96 seqs/block, grid 125 (exact single wave).
// warp m-tile = 16 rows x 256 gate cols; fp16 hi/lo split, 3 MMA products.
template<int LAYER>
__global__ void __launch_bounds__(192, 1) lstm_mma_kernel(
    const float* __restrict__ x, const float* __restrict__ Wih,
    const float* __restrict__ Whh, const float* __restrict__ bih,
    const float* __restrict__ bhh)
{
    constexpr int KT = LAYER ? 8 : 4;
    extern __shared__ char smraw[];
    __half* Whi   = (__half*)smraw;                   // [KT*16][264]
    __half* Wlo   = (__half*)(smraw + 67584);
    __half* Hhi0  = (__half*)(smraw + 135168);        // [96][72] each
    __half* Hhi1  = (__half*)(smraw + 148992);
    __half* Hlo0  = (__half*)(smraw + 162816);
    __half* Hlo1  = (__half*)(smraw + 176640);
    __half* H0hi  = (__half*)(smraw + 190464);
    __half* H0lo  = (__half*)(smraw + 204288);
    float* bias_s = (float*)(smraw + 218112);         // [256]
    float* wih_s  = (float*)(smraw + 219136);         // [256] (layer0)
    float* x_s    = (float*)(smraw + 220160);         // [12][96] (layer0)

    const int tid = threadIdx.x;
    const int sb = blockIdx.x * 96;

    for (int i = tid; i < KT * 16 * 256; i += 192) {
        int k = i >> 8, n = i & 255;
        float w = (LAYER && k >= 64) ? Wih[n * 64 + (k - 64)] : Whh[n * 64 + k];
        __half h = __float2half_rn(w);
        Whi[k * 264 + n] = h;
        Wlo[k * 264 + n] = __float2half_rn(w - __half2float(h));
    }
    for (int i = tid; i < 256; i += 192) {
        bias_s[i] = bih[i] + bhh[i];
        if (!LAYER) wih_s[i] = Wih[i];
    }
    if (!LAYER) {
        for (int i = tid; i < TT * 96; i += 192) {
            int t = i / 96, sl = i - t * 96;
            int seq = sb + sl, b = seq / NN, n = seq - b * NN;
            x_s[i] = x[(b * TT + t) * NN + n];
        }
    }
    for (int i = tid; i < 3456; i += 192) {
        ((unsigned*)Hhi0)[i] = 0u; ((unsigned*)Hlo0)[i] = 0u;
    }
    __syncthreads();

    const int wid = tid >> 5, lane = tid & 31;
    const int r0 = wid * 16;
    const int lp = lane & 3, rbase = lane >> 2;
    const unsigned a_off  = (unsigned)(((r0 + (lane & 15)) * 72 + (lane >> 4) * 8) * 2);
    const unsigned w_off  = (unsigned)(((lane & 15) * 264 + (lane >> 4) * 8) * 2);
    const unsigned whi_b  = smem_u32(Whi) + w_off;
    const unsigned wlo_b  = smem_u32(Wlo) + w_off;
    const unsigned h0hi_b = smem_u32(H0hi) + a_off;
    const unsigned h0lo_b = smem_u32(H0lo) + a_off;

    float cst[32];
#pragma unroll
    for (int i = 0; i < 32; i++) cst[i] = 0.0f;

    for (int t = 0; t < TT; t++) {
        if (LAYER) {
            for (int i = tid; i < 3072; i += 192) {   // stage h0(t): 96 x 64
                int row = i >> 5, c2 = (i & 31) * 2;
                uint2 v = *(const uint2*)&g_h0p[(t * BNS + sb + row) * 64 + c2];
                __half2 va = *(__half2*)&v.x, vb = *(__half2*)&v.y;
                *(__half2*)&H0hi[row * 72 + c2] = __halves2half2(__low2half(va),  __low2half(vb));
                *(__half2*)&H0lo[row * 72 + c2] = __halves2half2(__high2half(va), __high2half(vb));
            }
            __syncthreads();
        }
        const bool rb = (t & 1);
        const unsigned ahi_b = smem_u32(rb ? Hhi1 : Hhi0) + a_off;
        const unsigned alo_b = smem_u32(rb ? Hlo1 : Hlo0) + a_off;
        __half* WHhi = rb ? Hhi0 : Hhi1;
        __half* WHlo = rb ? Hlo0 : Hlo1;

        float acc[32][4];
#pragma unroll
        for (int i = 0; i < 32; i++) { acc[i][0]=0.f; acc[i][1]=0.f; acc[i][2]=0.f; acc[i][3]=0.f; }

#pragma unroll
        for (int kt = 0; kt < KT; kt++) {
            unsigned ah0, ah1, ah2, ah3, al0, al1, al2, al3;
            if (kt < 4) {
                ldsm_x4(ah0, ah1, ah2, ah3, ahi_b + kt * 32);
                ldsm_x4(al0, al1, al2, al3, alo_b + kt * 32);
            } else {
                ldsm_x4(ah0, ah1, ah2, ah3, h0hi_b + (kt - 4) * 32);
                ldsm_x4(al0, al1, al2, al3, h0lo_b + (kt - 4) * 32);
            }
            const unsigned wrow = (unsigned)(kt * 16 * 264 * 2);
#pragma unroll
            for (int n2 = 0; n2 < 16; n2++) {         // Ahi * Bhi
                unsigned b0, b1, b2, b3;
                ldsm_x4t(b0, b1, b2, b3, whi_b + wrow + n2 * 32);
                MMA2(n2, b0, b1, b2, b3, ah0, ah1, ah2, ah3);
            }
#pragma unroll
            for (int n2 = 0; n2 < 16; n2++) {         // Ahi * Blo
                unsigned b0, b1, b2, b3;
                ldsm_x4t(b0, b1, b2, b3, wlo_b + wrow + n2 * 32);
                MMA2(n2, b0, b1, b2, b3, ah0, ah1, ah2, ah3);
            }
#pragma unroll
            for (int n2 = 0; n2 < 16; n2++) {         // Alo * Bhi
                unsigned b0, b1, b2, b3;
                ldsm_x4t(b0, b1, b2, b3, whi_b + wrow + n2 * 32);
                MMA2(n2, b0, b1, b2, b3, al0, al1, al2, al3);
            }
        }

        // epilogue: cols of acc[nt][2*rs+j] = nt*8 + 2*lp + j, rows r0+rbase+8*rs
#pragma unroll
        for (int rs = 0; rs < 2; rs++) {
            const int r = r0 + rbase + rs * 8;
            const int seq = sb + r;
            const float xr = LAYER ? 0.0f : x_s[t * 96 + r];
#pragma unroll
            for (int k8 = 0; k8 < 8; k8++) {
                __half hhi[2], hlo[2];
#pragma unroll
                for (int j = 0; j < 2; j++) {
                    const int u = k8 * 8 + 2 * lp + j;
                    const int ai = 2 * rs + j;
                    float gi = acc[k8][ai]      + bias_s[u];
                    float gf = acc[8 + k8][ai]  + bias_s[64 + u];
                    float gg = acc[16 + k8][ai] + bias_s[128 + u];
                    float go = acc[24 + k8][ai] + bias_s[192 + u];
                    if (!LAYER) {
                        gi += wih_s[u] * xr;        gf += wih_s[64 + u] * xr;
                        gg += wih_s[128 + u] * xr;  go += wih_s[192 + u] * xr;
                    }
                    float c = cst[k8 * 4 + rs * 2 + j];
                    c = sigf(gf) * c + sigf(gi) * tanh_f(gg);
                    cst[k8 * 4 + rs * 2 + j] = c;
                    float h = sigf(go) * tanh_f(c);
                    hhi[j] = __float2half_rn(h);
                    hlo[j] = __float2half_rn(h - __half2float(hhi[j]));
                    if (LAYER && t == TT - 1) g_h[seq * 64 + u] = h;
                }
                const int uc = k8 * 8 + 2 * lp;
                *(__half2*)&WHhi[r * 72 + uc] = __halves2half2(hhi[0], hhi[1]);
                *(__half2*)&WHlo[r * 72 + uc] = __halves2half2(hlo[0], hlo[1]);
                if (!LAYER) {
                    __half2 p0 = __halves2half2(hhi[0], hlo[0]);
                    __half2 p1 = __halves2half2(hhi[1], hlo[1]);
                    uint2 pv = make_uint2(*(unsigned*)&p0, *(unsigned*)&p1);
                    *(uint2*)&g_h0p[(t * BNS + seq) * 64 + uc] = pv;
                }
            }
        }
        __syncthreads();
    }
}

// ================= GAT prep: hp(fp16) = h @ W^T, e_src, e_dst =================
__global__ void __launch_bounds__(256) gat_prep_kernel(
    const float* __restrict__ hin, const float* __restrict__ W,
    const float* __restrict__ asrc, const float* __restrict__ adst)
{
    __shared__ float W_s[64 * 65];
    __shared__ float hin_s[4][64];
    __shared__ float hp_s[4][64];
    __shared__ float as_s[64], ad_s[64];
    const int tid = threadIdx.x;
    for (int i = tid; i < 4096; i += 256) W_s[(i >> 6) * 65 + (i & 63)] = W[i];
    const int ri = tid >> 6, k = tid & 63;
    const int r = blockIdx.x * 4 + ri;
    hin_s[ri][k] = hin[r * 64 + k];
    if (tid < 64) as_s[tid] = asrc[tid];
    else if (tid < 128) ad_s[tid - 64] = adst[tid - 64];
    __syncthreads();
    float acc = 0.0f;
#pragma unroll
    for (int c = 0; c < 64; c++) acc += W_s[k * 65 + c] * hin_s[ri][c];
    g_hph[r * 64 + k] = __float2half(acc);
    hp_s[ri][k] = acc;
    __syncthreads();
    if (tid < 32) {
        int rri = tid >> 3, h = (tid >> 1) & 3, w = tid & 1;
        const float* a = w ? ad_s : as_s;
        float d = 0.0f;
#pragma unroll
        for (int dd = 0; dd < 16; dd++) d += hp_s[rri][h * 16 + dd] * a[h * 16 + dd];
        int rr = blockIdx.x * 4 + rri;
        if (w) g_ed[rr * 4 + h] = d; else g_es[rr * 4 + h] = d;
    }
}

// ================= global per-(b,h) max of ed =================
__global__ void __launch_bounds__(256) gmax_kernel() {
    const int w = blockIdx.x;          // 0..31
    const int b = w >> 2, h = w & 3;
    __shared__ float red[8];
    const int tid = threadIdx.x;
    float m = -1e30f;
    for (int j = tid; j < NN; j += 256)
        m = fmaxf(m, g_ed[(b * NN + j) * 4 + h]);
#pragma unroll
    for (int off = 16; off; off >>= 1)
        m = fmaxf(m, __shfl_xor_sync(0xffffffffu, m, off));
    if ((tid & 31) == 0) red[tid >> 5] = m;
    __syncthreads();
    if (tid == 0) {
        float mm = red[0];
#pragma unroll
        for (int i = 1; i < 8; i++) mm = fmaxf(mm, red[i]);
        g_gmax[w] = mm;
    }
}

// ================= GAT softmax + aggregate via mma.m16n8k16 =================
#define NTJ 24
__global__ void __launch_bounds__(256, 2) gat_agg2_kernel(
    const int* __restrict__ adj, float* __restrict__ out)
{
    extern __shared__ char smc[];
    __half* hp_s = (__half*)smc;                    // [64][72]      9216 B
    __half* p_s  = (__half*)(smc + 9216);           // [8][16][72]  18432 B
    float* ed_s  = (float*)(smc + 27648);           // [1536][4]    24576 B
    unsigned* adjm = (unsigned*)(smc + 52224);      // [64]           256 B
    float* psum_s  = (float*)(smc + 52480);         // [8][16]        512 B

    const int tid = threadIdx.x;
    const int b = blockIdx.y;
    const int i0 = blockIdx.x * 32;
    const int warp = tid >> 5, lane = tid & 31;
    const int h_w = warp & 3, seg = warp >> 2;
    const int iw0 = i0 + seg * 16;
    const int i_loc = lane >> 1, jhalf = lane & 1;
    const int i_row = iw0 + i_loc;
    const int irc = (i_row < NN) ? i_row : NN - 1;

    for (int idx = tid; idx < 1536; idx += 256) {
        float4 v = make_float4(0.f, 0.f, 0.f, 0.f);
        if (idx < NN) v = reinterpret_cast<const float4*>(g_ed)[b * NN + idx];
        reinterpret_cast<float4*>(ed_s)[idx] = v;
    }

    const float es = g_es[(b * NN + irc) * 4 + h_w];
    const float M  = lrelu(es + g_gmax[b * 4 + h_w]);

    __half* pw = p_s + warp * (16 * 72);
    const unsigned pw_b  = smem_u32(pw);
    const unsigned hps_b = smem_u32(hp_s);

    float acc[8];
#pragma unroll
    for (int i = 0; i < 8; i++) acc[i] = 0.0f;
    float psl = 0.0f;

    for (int jt = 0; jt < NTJ; jt++) {
        const int jb = jt * 64;
        __syncthreads();
        for (int k = tid; k < 512; k += 256) {
            int jl = k >> 3, co = (k & 7) * 8;
            int j = jb + jl;
            uint4 v = make_uint4(0u, 0u, 0u, 0u);
            if (j < NN) v = *reinterpret_cast<const uint4*>(&g_hph[(b * NN + j) * 64 + co]);
            *reinterpret_cast<uint4*>(&hp_s[jl * 72 + co]) = v;
        }
#pragma unroll
        for (int p = 0; p < 8; p++) {
            int word = warp * 8 + p;
            int ii = i0 + (word >> 1);
            int jj = jb + (word & 1) * 32 + lane;
            int a = (ii < NN && jj < NN) ? adj[ii * NN + jj] : 0;
            unsigned m = __ballot_sync(0xffffffffu, a > 0);
            if (lane == 0) adjm[word] = m;
        }
        __syncthreads();

        {
            unsigned mword = adjm[(seg * 16 + i_loc) * 2 + jhalf];
            const float* edp = ed_s + (jb + jhalf * 32) * 4 + h_w;
            __half2* pst = reinterpret_cast<__half2*>(pw + i_loc * 72 + jhalf * 32);
#pragma unroll
            for (int q = 0; q < 32; q += 2) {
                float m0 = (float)((mword >> q) & 1u);
                float m1 = (float)((mword >> (q + 1)) & 1u);
                float p0 = m0 * __expf(lrelu(es + edp[q * 4]) - M);
                float p1 = m1 * __expf(lrelu(es + edp[(q + 1) * 4]) - M);
                psl += p0 + p1;
                pst[q >> 1] = __floats2half2_rn(p0, p1);
            }
        }
        __syncwarp();

        const unsigned a_addr0 = pw_b + (lane & 15) * 144 + ((lane >> 4) * 8) * 2;
        const unsigned b_addr0 = hps_b + ((lane & 15) * 72 + h_w * 16 + (lane >> 4) * 8) * 2;
#pragma unroll
        for (int kt = 0; kt < 4; kt++) {
            unsigned a0, a1, a2, a3, b0, b1, b2, b3;
            ldsm_x4 (a0, a1, a2, a3, a_addr0 + kt * 32);
            ldsm_x4t(b0, b1, b2, b3, b_addr0 + kt * 16 * 144);
            mma16816(acc[0], acc[1], acc[2], acc[3], a0, a1, a2, a3, b0, b1);
            mma16816(acc[4], acc[5], acc[6], acc[7], a0, a1, a2, a3, b2, b3);
        }
    }

    psl += __shfl_xor_sync(0xffffffffu, psl, 1);
    if (jhalf == 0) psum_s[warp * 16 + i_loc] = psl;
    __syncwarp();

    const int r_lo = iw0 + (lane >> 2), r_hi = r_lo + 8;
    const float inv_lo = 1.0f / psum_s[warp * 16 + (lane >> 2)];
    const float inv_hi = 1.0f / psum_s[warp * 16 + (lane >> 2) + 8];
    const int cb = h_w * 16 + (lane & 3) * 2;
    if (r_lo < NN) {
        *reinterpret_cast<float2*>(&out[(b * NN + r_lo) * 64 + cb]) =
            make_float2(fmaxf(acc[0] * inv_lo, 0.f), fmaxf(acc[1] * inv_lo, 0.f));
        *reinterpret_cast<float2*>(&out[(b * NN + r_lo) * 64 + cb + 8]) =
            make_float2(fmaxf(acc[4] * inv_lo, 0.f), fmaxf(acc[5] * inv_lo, 0.f));
    }
    if (r_hi < NN) {
        *reinterpret_cast<float2*>(&out[(b * NN + r_hi) * 64 + cb]) =
            make_float2(fmaxf(acc[2] * inv_hi, 0.f), fmaxf(acc[3] * inv_hi, 0.f));
        *reinterpret_cast<float2*>(&out[(b * NN + r_hi) * 64 + cb + 8]) =
            make_float2(fmaxf(acc[6] * inv_hi, 0.f), fmaxf(acc[7] * inv_hi, 0.f));
    }
}

// ================= output head =================
__global__ void __launch_bounds__(256) head_kernel(
    const float* __restrict__ oW, const float* __restrict__ ob,
    float* __restrict__ out)
{
    int s = blockIdx.x * 256 + threadIdx.x;
    if (s >= BNS) return;
    int b = s / NN, n = s % NN;
    float a0 = ob[0], a1 = ob[1], a2 = ob[2];
#pragma unroll 8
    for (int c = 0; c < 64; c++) {
        float v = g_h2[s * 64 + c];
        a0 += oW[c] * v; a1 += oW[64 + c] * v; a2 += oW[128 + c] * v;
    }
    out[(b * OUTD + 0) * NN + n] = a0;
    out[(b * OUTD + 1) * NN + n] = a1;
    out[(b * OUTD + 2) * NN + n] = a2;
}

extern "C" void kernel_launch(void* const* d_in, const int* in_sizes, int n_in,
                              void* d_out, int out_size) {
    const float* x    = (const float*)d_in[0];
    const int*   adj  = (const int*)  d_in[1];
    const float* Wih0 = (const float*)d_in[2];
    const float* Whh0 = (const float*)d_in[3];
    const float* bih0 = (const float*)d_in[4];
    const float* bhh0 = (const float*)d_in[5];
    const float* Wih1 = (const float*)d_in[6];
    const float* Whh1 = (const float*)d_in[7];
    const float* bih1 = (const float*)d_in[8];
    const float* bhh1 = (const float*)d_in[9];
    const float* g0W  = (const float*)d_in[10];
    const float* g0as = (const float*)d_in[11];
    const float* g0ad = (const float*)d_in[12];
    const float* g1W  = (const float*)d_in[13];
    const float* g1as = (const float*)d_in[14];
    const float* g1ad = (const float*)d_in[15];
    const float* outW = (const float*)d_in[16];
    const float* outb = (const float*)d_in[17];
    float* out = (float*)d_out;

    cudaFuncSetAttribute(lstm_mma_kernel<0>, cudaFuncAttributeMaxDynamicSharedMemorySize, 224768);
    cudaFuncSetAttribute(lstm_mma_kernel<1>, cudaFuncAttributeMaxDynamicSharedMemorySize, 224768);
    cudaFuncSetAttribute(gat_agg2_kernel,    cudaFuncAttributeMaxDynamicSharedMemorySize, 52992);

    float* g_h_p;  cudaGetSymbolAddress((void**)&g_h_p,  g_h);
    float* g_ho_p; cudaGetSymbolAddress((void**)&g_ho_p, g_ho);
    float* g_h2_p; cudaGetSymbolAddress((void**)&g_h2_p, g_h2);

    lstm_mma_kernel<0><<<125, 192, 224768>>>(x, Wih0, Whh0, bih0, bhh0);
    lstm_mma_kernel<1><<<125, 192, 224768>>>(x, Wih1, Whh1, bih1, bhh1);

    gat_prep_kernel<<<3000, 256>>>(g_h_p, g0W, g0as, g0ad);
    gmax_kernel<<<32, 256>>>();
    gat_agg2_kernel<<<dim3(47, 8), 256, 52992>>>(adj, g_ho_p);

    gat_prep_kernel<<<3000, 256>>>(g_ho_p, g1W, g1as, g1ad);
    gmax_kernel<<<32, 256>>>();
    gat_agg2_kernel<<<dim3(47, 8), 256, 52992>>>(adj, g_h2_p);

    head_kernel<<<47, 256>>>(outW, outb, out);
}